// round 1
// baseline (speedup 1.0000x reference)
#include <cuda_runtime.h>
#include <cuda_bf16.h>

// ---------------- static scratch (no allocations allowed) ----------------
// x: [64,512,28,28]; theta/g/phi conv outs: [64,256,784]; pooled: [64,256,196]
// M: [8,256,256]; y: [64,256,784]; z: [64,512,784]; stats: 512 sums + 512 sumsqs
__device__ float theta_buf[64 * 256 * 784];
__device__ float gpre_buf [64 * 256 * 784];
__device__ float ppre_buf [64 * 256 * 784];
__device__ float gpool_buf[64 * 256 * 196];
__device__ float ppool_buf[64 * 256 * 196];
__device__ float Mmat_buf [8 * 256 * 256];
__device__ float y_buf    [64 * 256 * 784];
__device__ float z_buf    [64 * 512 * 784];
__device__ float g_stats  [1024];

// ---------------- conv1x1 GEMM body: C[64 x 56] = W[64 x K] @ X[K x 784] tile ----
// blockDim = (14, 16), 224 threads, each thread computes 4x4.
template <int K>
__device__ __forceinline__ void conv_gemm_body(
    const float* __restrict__ W,    // region base, row-major, ld = K
    const float* __restrict__ X,    // [K, 784] row-major
    const float* __restrict__ bias, // region base
    float* __restrict__ out,        // already offset to (region_row)*784
    int n0)
{
    __shared__ float As[16][64];
    __shared__ float Bs[16][56];
    float acc[4][4] = {};

    const int tx = threadIdx.x;            // 0..13
    const int ty = threadIdx.y;            // 0..15
    const int tid = ty * 14 + tx;          // 0..223
    const int bk = tid / 14;               // 0..15
    const int bn = (tid % 14) * 4;         // 0..52

    for (int k0 = 0; k0 < K; k0 += 16) {
        // A tile: 64 rows x 16 k = 256 float4 over 224 threads
        for (int i = tid; i < 256; i += 224) {
            int m = i >> 2, kq = (i & 3) * 4;
            float4 v = *reinterpret_cast<const float4*>(W + m * K + k0 + kq);
            As[kq + 0][m] = v.x; As[kq + 1][m] = v.y;
            As[kq + 2][m] = v.z; As[kq + 3][m] = v.w;
        }
        // B tile: 16 x 56 = 224 float4, exactly one per thread
        *reinterpret_cast<float4*>(&Bs[bk][bn]) =
            *reinterpret_cast<const float4*>(X + (k0 + bk) * 784 + n0 + bn);
        __syncthreads();

#pragma unroll
        for (int k = 0; k < 16; k++) {
            float4 a = *reinterpret_cast<float4*>(&As[k][ty * 4]);
            float4 b = *reinterpret_cast<float4*>(&Bs[k][tx * 4]);
            acc[0][0] += a.x * b.x; acc[0][1] += a.x * b.y; acc[0][2] += a.x * b.z; acc[0][3] += a.x * b.w;
            acc[1][0] += a.y * b.x; acc[1][1] += a.y * b.y; acc[1][2] += a.y * b.z; acc[1][3] += a.y * b.w;
            acc[2][0] += a.z * b.x; acc[2][1] += a.z * b.y; acc[2][2] += a.z * b.z; acc[2][3] += a.z * b.w;
            acc[3][0] += a.w * b.x; acc[3][1] += a.w * b.y; acc[3][2] += a.w * b.z; acc[3][3] += a.w * b.w;
        }
        __syncthreads();
    }

#pragma unroll
    for (int i = 0; i < 4; i++) {
        float bi = bias[ty * 4 + i];
#pragma unroll
        for (int j = 0; j < 4; j++)
            out[(ty * 4 + i) * 784 + n0 + tx * 4 + j] = acc[i][j] + bi;
    }
}

// ---------------- kernel 1: three projections fused (theta | g | phi) ------
// grid (14, 12, 64); blockIdx.y tiles of 64 rows over 768 combined out-channels
__global__ __launch_bounds__(224) void proj_gemm(
    const float* __restrict__ x,
    const float* __restrict__ wth, const float* __restrict__ bth,
    const float* __restrict__ wg,  const float* __restrict__ bg,
    const float* __restrict__ wph, const float* __restrict__ bph)
{
    const int nimg = blockIdx.z;
    const int m0 = blockIdx.y * 64;
    const int n0 = blockIdx.x * 56;
    const float* W; const float* bias; float* out;
    if (m0 < 256)      { W = wth + m0 * 512;          bias = bth + m0;          out = theta_buf + nimg * 200704 + m0 * 784; }
    else if (m0 < 512) { int r = m0 - 256; W = wg + r * 512;  bias = bg + r;    out = gpre_buf  + nimg * 200704 + r * 784; }
    else               { int r = m0 - 512; W = wph + r * 512; bias = bph + r;   out = ppre_buf  + nimg * 200704 + r * 784; }
    conv_gemm_body<512>(W, x + nimg * 401408, bias, out, n0);
}

// ---------------- kernel 2: 2x2 maxpool (g and phi) -----------------------
// grid (12544, 2), 256 thr; one output element per thread
__global__ void pool_kernel()
{
    const int idx = blockIdx.x * 256 + threadIdx.x;        // 0..3211263
    const float* in = blockIdx.y ? ppre_buf : gpre_buf;
    float* outp     = blockIdx.y ? ppool_buf : gpool_buf;
    int pw = idx % 14;
    int r  = idx / 14;
    int ph = r % 14;
    r /= 14;                                                // r = nimg*256 + c
    const float* p = in + r * 784 + ph * 56 + pw * 2;
    outp[idx] = fmaxf(fmaxf(p[0], p[1]), fmaxf(p[28], p[29]));
}

// ---------------- kernel 3: M[b] = (Phi_b @ G_b^T) / 1568  ([256x1568]x[1568x256])
// grid (4, 4, 8); blockDim (16,16)
__global__ __launch_bounds__(256) void gemm_nt_M()
{
    const int b = blockIdx.z;
    const float* A  = ppool_buf + b * 401408;  // Phi_b [256,1568]
    const float* Bm = gpool_buf + b * 401408;  // G_b   [256,1568]
    const int i0 = blockIdx.y * 64;
    const int j0 = blockIdx.x * 64;

    __shared__ float As[16][64];
    __shared__ float Bs[16][64];
    float acc[4][4] = {};

    const int tx = threadIdx.x, ty = threadIdx.y;
    const int tid = ty * 16 + tx;
    const int lr = tid >> 2;           // 0..63
    const int lk = (tid & 3) * 4;      // 0,4,8,12

    for (int k0 = 0; k0 < 1568; k0 += 16) {
        float4 av = *reinterpret_cast<const float4*>(A  + (i0 + lr) * 1568 + k0 + lk);
        float4 bv = *reinterpret_cast<const float4*>(Bm + (j0 + lr) * 1568 + k0 + lk);
        As[lk + 0][lr] = av.x; As[lk + 1][lr] = av.y; As[lk + 2][lr] = av.z; As[lk + 3][lr] = av.w;
        Bs[lk + 0][lr] = bv.x; Bs[lk + 1][lr] = bv.y; Bs[lk + 2][lr] = bv.z; Bs[lk + 3][lr] = bv.w;
        __syncthreads();
#pragma unroll
        for (int k = 0; k < 16; k++) {
            float4 a = *reinterpret_cast<float4*>(&As[k][ty * 4]);
            float4 b2 = *reinterpret_cast<float4*>(&Bs[k][tx * 4]);
            acc[0][0] += a.x * b2.x; acc[0][1] += a.x * b2.y; acc[0][2] += a.x * b2.z; acc[0][3] += a.x * b2.w;
            acc[1][0] += a.y * b2.x; acc[1][1] += a.y * b2.y; acc[1][2] += a.y * b2.z; acc[1][3] += a.y * b2.w;
            acc[2][0] += a.z * b2.x; acc[2][1] += a.z * b2.y; acc[2][2] += a.z * b2.z; acc[2][3] += a.z * b2.w;
            acc[3][0] += a.w * b2.x; acc[3][1] += a.w * b2.y; acc[3][2] += a.w * b2.z; acc[3][3] += a.w * b2.w;
        }
        __syncthreads();
    }

    float* C = Mmat_buf + b * 65536;
    const float inv = 1.0f / 1568.0f;
#pragma unroll
    for (int i = 0; i < 4; i++)
#pragma unroll
        for (int j = 0; j < 4; j++)
            C[(i0 + ty * 4 + i) * 256 + j0 + tx * 4 + j] = acc[i][j] * inv;
}

// ---------------- kernel 4: y[b] = Theta_b^T @ M_b, with view-unscramble store
// Theta_b storage [256(ci), 6272(t)], M_b [256,256]. grid (4, 98, 8); blockDim (16,16)
__global__ __launch_bounds__(256) void gemm_tn_y()
{
    const int b = blockIdx.z;
    const float* A  = theta_buf + b * 1605632;   // A[k][m], ld 6272
    const float* Bm = Mmat_buf  + b * 65536;     // B[k][n], ld 256
    const int m0 = blockIdx.y * 64;              // t
    const int n0 = blockIdx.x * 64;              // ci'

    __shared__ float As[16][64];
    __shared__ float Bs[16][64];
    float acc[4][4] = {};

    const int tx = threadIdx.x, ty = threadIdx.y;
    const int tid = ty * 16 + tx;
    const int lk = tid >> 4;           // 0..15
    const int lq = (tid & 15) * 4;     // 0..60

    for (int k0 = 0; k0 < 256; k0 += 16) {
        *reinterpret_cast<float4*>(&As[lk][lq]) =
            *reinterpret_cast<const float4*>(A + (k0 + lk) * 6272 + m0 + lq);
        *reinterpret_cast<float4*>(&Bs[lk][lq]) =
            *reinterpret_cast<const float4*>(Bm + (k0 + lk) * 256 + n0 + lq);
        __syncthreads();
#pragma unroll
        for (int k = 0; k < 16; k++) {
            float4 a = *reinterpret_cast<float4*>(&As[k][ty * 4]);
            float4 b2 = *reinterpret_cast<float4*>(&Bs[k][tx * 4]);
            acc[0][0] += a.x * b2.x; acc[0][1] += a.x * b2.y; acc[0][2] += a.x * b2.z; acc[0][3] += a.x * b2.w;
            acc[1][0] += a.y * b2.x; acc[1][1] += a.y * b2.y; acc[1][2] += a.y * b2.z; acc[1][3] += a.y * b2.w;
            acc[2][0] += a.z * b2.x; acc[2][1] += a.z * b2.y; acc[2][2] += a.z * b2.z; acc[2][3] += a.z * b2.w;
            acc[3][0] += a.w * b2.x; acc[3][1] += a.w * b2.y; acc[3][2] += a.w * b2.z; acc[3][3] += a.w * b2.w;
        }
        __syncthreads();
    }

    // y element (b, t=m, ci'=n) -> conv layout [64,256,784]:
    //   n_img = 8b + (n>>5); c = (n&31)*8 + t/784; s = t%784
#pragma unroll
    for (int i = 0; i < 4; i++) {
        int m = m0 + ty * 4 + i;
        int tq = m / 784, s = m % 784;
#pragma unroll
        for (int j = 0; j < 4; j++) {
            int n = n0 + tx * 4 + j;
            int dst = (8 * b + (n >> 5)) * 200704 + ((n & 31) * 8 + tq) * 784 + s;
            y_buf[dst] = acc[i][j];
        }
    }
}

// ---------------- kernel 5: z = conv1x1(y, wW, bW). grid (14, 8, 64) -------
__global__ __launch_bounds__(224) void z_gemm(const float* __restrict__ wW,
                                              const float* __restrict__ bW)
{
    const int nimg = blockIdx.z;
    const int m0 = blockIdx.y * 64;
    const int n0 = blockIdx.x * 56;
    conv_gemm_body<256>(wW + m0 * 256, y_buf + nimg * 200704, bW + m0,
                        z_buf + nimg * 401408 + m0 * 784, n0);
}

// ---------------- kernel 6: per-channel BN stats (deterministic) -----------
__global__ __launch_bounds__(256) void bn_stats()
{
    const int c = blockIdx.x;   // 0..511
    float s1 = 0.f, s2 = 0.f;
    const float* base = z_buf + c * 784;
    for (int n = 0; n < 64; n++) {
        const float* p = base + n * 401408;
        for (int s = threadIdx.x; s < 784; s += 256) {
            float v = p[s];
            s1 += v; s2 += v * v;
        }
    }
    __shared__ float r1[256], r2[256];
    r1[threadIdx.x] = s1; r2[threadIdx.x] = s2;
    __syncthreads();
    for (int off = 128; off > 0; off >>= 1) {
        if (threadIdx.x < off) {
            r1[threadIdx.x] += r1[threadIdx.x + off];
            r2[threadIdx.x] += r2[threadIdx.x + off];
        }
        __syncthreads();
    }
    if (threadIdx.x == 0) { g_stats[c] = r1[0]; g_stats[512 + c] = r2[0]; }
}

// ---------------- kernel 7: out = BN(z)*gamma+beta + x. grid 25088x256 -----
__global__ __launch_bounds__(256) void bn_res(
    const float* __restrict__ x,
    const float* __restrict__ gamma, const float* __restrict__ beta,
    float* __restrict__ out)
{
    const int i4 = blockIdx.x * 256 + threadIdx.x;  // float4 index, 6422528 total
    const int c = (i4 / 196) & 511;                  // channel (784 floats = 196 float4)
    const float inv_cnt = 1.0f / 50176.0f;
    float mean = g_stats[c] * inv_cnt;
    float var  = g_stats[512 + c] * inv_cnt - mean * mean;
    float sc = gamma[c] * rsqrtf(var + 1e-5f);
    float sh = beta[c] - mean * sc;
    float4 zv = reinterpret_cast<const float4*>(z_buf)[i4];
    float4 xv = reinterpret_cast<const float4*>(x)[i4];
    float4 o;
    o.x = zv.x * sc + sh + xv.x;
    o.y = zv.y * sc + sh + xv.y;
    o.z = zv.z * sc + sh + xv.z;
    o.w = zv.w * sc + sh + xv.w;
    reinterpret_cast<float4*>(out)[i4] = o;
}

// ---------------- launcher -------------------------------------------------
extern "C" void kernel_launch(void* const* d_in, const int* in_sizes, int n_in,
                              void* d_out, int out_size)
{
    const float* x     = (const float*)d_in[0];
    const float* wg    = (const float*)d_in[1];
    const float* bg    = (const float*)d_in[2];
    const float* wth   = (const float*)d_in[3];
    const float* bth   = (const float*)d_in[4];
    const float* wph   = (const float*)d_in[5];
    const float* bph   = (const float*)d_in[6];
    const float* wW    = (const float*)d_in[7];
    const float* bW    = (const float*)d_in[8];
    const float* gamma = (const float*)d_in[9];
    const float* beta  = (const float*)d_in[10];
    float* out = (float*)d_out;

    proj_gemm<<<dim3(14, 12, 64), dim3(14, 16)>>>(x, wth, bth, wg, bg, wph, bph);
    pool_kernel<<<dim3(12544, 2), 256>>>();
    gemm_nt_M<<<dim3(4, 4, 8), dim3(16, 16)>>>();
    gemm_tn_y<<<dim3(4, 98, 8), dim3(16, 16)>>>();
    z_gemm<<<dim3(14, 8, 64), dim3(14, 16)>>>(wW, bW);
    bn_stats<<<512, 256>>>();
    bn_res<<<25088, 256>>>(x, gamma, beta, out);
}

// round 3
// speedup vs baseline: 1.9576x; 1.9576x over previous
#include <cuda_runtime.h>
#include <cuda_bf16.h>
#include <cstdint>

// ====================== mma.sync helpers (sm_103 baseline ISA) ======================
__device__ __forceinline__ uint32_t smem_to_u32(const void* smem_ptr) {
    uint32_t addr;
    asm("{ .reg .u64 tmp; cvta.to.shared.u64 tmp, %1; cvt.u32.u64 %0, tmp; }"
        : "=r"(addr) : "l"(smem_ptr));
    return addr;
}
__device__ __forceinline__ void ldsm_x4(uint32_t* r, uint32_t addr) {
    asm volatile("ldmatrix.sync.aligned.m8n8.x4.shared.b16 {%0,%1,%2,%3}, [%4];"
        : "=r"(r[0]), "=r"(r[1]), "=r"(r[2]), "=r"(r[3]) : "r"(addr));
}
__device__ __forceinline__ void ldsm_x2(uint32_t* r, uint32_t addr) {
    asm volatile("ldmatrix.sync.aligned.m8n8.x2.shared.b16 {%0,%1}, [%2];"
        : "=r"(r[0]), "=r"(r[1]) : "r"(addr));
}
__device__ __forceinline__ void mma_16816(float* c, const uint32_t* a, const uint32_t* b) {
    asm volatile("mma.sync.aligned.m16n8k16.row.col.f32.bf16.bf16.f32 "
        "{%0,%1,%2,%3}, {%4,%5,%6,%7}, {%8,%9}, {%0,%1,%2,%3};"
        : "+f"(c[0]), "+f"(c[1]), "+f"(c[2]), "+f"(c[3])
        : "r"(a[0]), "r"(a[1]), "r"(a[2]), "r"(a[3]), "r"(b[0]), "r"(b[1]));
}
#define CP_ASYNC16(dst, src) \
    asm volatile("cp.async.cg.shared.global [%0], [%1], 16;" :: "r"(dst), "l"(src))
#define CP_COMMIT() asm volatile("cp.async.commit_group;" ::: "memory")
#define CP_WAIT(n)  asm volatile("cp.async.wait_group %0;" :: "n"(n) : "memory")

// ====================== static scratch ======================
__device__ float theta_buf[64 * 256 * 784];
__device__ float gpre_buf [64 * 256 * 784];
__device__ float ppre_buf [64 * 256 * 784];
__device__ float gpool_buf[64 * 256 * 196];
__device__ float ppool_buf[64 * 256 * 196];
__device__ float Mmat_buf [8 * 256 * 256];
__device__ float z_buf    [64 * 512 * 784];
__device__ float g_stats  [1024];

__device__ __nv_bfloat16 wcat_hi[768 * 512], wcat_lo[768 * 512];   // theta|g|phi weights
__device__ __nv_bfloat16 wW_hi [512 * 256],  wW_lo [512 * 256];
__device__ __nv_bfloat16 xt_hi [64 * 784 * 512], xt_lo[64 * 784 * 512];  // x transposed
__device__ __nv_bfloat16 yt_hi [64 * 784 * 256], yt_lo[64 * 784 * 256];  // y, K-major

// ====================== split/convert kernels ======================
__device__ __forceinline__ void split_store(float v, __nv_bfloat16* hi, __nv_bfloat16* lo,
                                            size_t idx) {
    __nv_bfloat16 h = __float2bfloat16(v);
    hi[idx] = h;
    lo[idx] = __float2bfloat16(v - __bfloat162float(h));
}

__global__ __launch_bounds__(256) void split_w_kernel(
    const float* __restrict__ wth, const float* __restrict__ wg,
    const float* __restrict__ wph, const float* __restrict__ wW)
{
    int i = blockIdx.x * 256 + threadIdx.x;       // 0..524287
    if (i < 393216) {
        int r = i >> 9, k = i & 511;
        const float* w = (r < 256) ? wth : (r < 512) ? wg : wph;
        split_store(w[(r & 255) * 512 + k], wcat_hi, wcat_lo, i);
    } else {
        int j = i - 393216;
        split_store(wW[j], wW_hi, wW_lo, j);
    }
}

// x [img][512][784] -> xt [img][784][512] bf16 hi/lo. grid (49,32,64) block (16,16)
__global__ __launch_bounds__(256) void split_x_kernel(const float* __restrict__ x)
{
    __shared__ float t[16][17];
    int img = blockIdx.z;
    int c0 = blockIdx.y * 16, s0 = blockIdx.x * 16;
    const float* src = x + ((size_t)img * 512 + c0) * 784 + s0;
    t[threadIdx.y][threadIdx.x] = src[threadIdx.y * 784 + threadIdx.x];
    __syncthreads();
    float v = t[threadIdx.x][threadIdx.y];
    size_t dst = ((size_t)img * 784 + s0 + threadIdx.y) * 512 + c0 + threadIdx.x;
    split_store(v, xt_hi, xt_lo, dst);
}

// ====================== mma.sync conv GEMM ======================
// Out[Mtot, 784] per image = A[Mtot, KDIM] @ B_img[784, KDIM]^T + bias
// bf16x3 split-fp32. CTA tile 128x112, BK=32, 4-stage cp.async pipeline.
// 8 warps: 4(M) x 2(N); warp tile 32x56 (2 m16 x 7 n8 frags).
static constexpr int TC_STAGES = 4;
static constexpr int STAGE_ELEMS = 480 * 40;            // (256 A-rows + 224 B-rows) * 40
static constexpr int TC_SMEM = TC_STAGES * STAGE_ELEMS * 2;  // 153600 bytes

template <int KDIM>
__global__ __launch_bounds__(256, 1) void mma_conv_gemm(
    const __nv_bfloat16* __restrict__ Ahi, const __nv_bfloat16* __restrict__ Alo,
    const __nv_bfloat16* __restrict__ Bhi, const __nv_bfloat16* __restrict__ Blo,
    float* __restrict__ out0, float* __restrict__ out1, float* __restrict__ out2,
    const float* __restrict__ bias0, const float* __restrict__ bias1,
    const float* __restrict__ bias2, int rowsPerRegion)
{
    constexpr int KITERS = KDIM / 32;
    extern __shared__ __align__(128) __nv_bfloat16 smem[];
    const uint32_t smem_base = smem_to_u32(smem);

    const int tid = threadIdx.x;
    const int lane = tid & 31;
    const int wid = tid >> 5;
    const int warp_m = wid & 3;        // 0..3 -> m offset *32
    const int warp_n = wid >> 2;       // 0..1 -> n offset *56
    const int img = blockIdx.z;
    const int m0 = blockIdx.y * 128;
    const int n0 = blockIdx.x * 112;

    const __nv_bfloat16* A_hi = Ahi + (size_t)m0 * KDIM;
    const __nv_bfloat16* A_lo = Alo + (size_t)m0 * KDIM;
    const __nv_bfloat16* B_hi = Bhi + ((size_t)img * 784 + n0) * KDIM;
    const __nv_bfloat16* B_lo = Blo + ((size_t)img * 784 + n0) * KDIM;

    // ---- stage loader: 1920 x 16B chunks ----
    auto load_stage = [&](int st, int k0) {
        const uint32_t sb = smem_base + (uint32_t)(st * STAGE_ELEMS * 2);
        for (int i = tid; i < 1920; i += 256) {
            int row, kc;
            const __nv_bfloat16* src;
            int dst_row;
            if (i < 1024) {
                int d = i >> 9, j = i & 511;
                row = j >> 2; kc = j & 3;
                src = (d ? A_lo : A_hi) + (size_t)row * KDIM + k0 + kc * 8;
                dst_row = d * 128 + row;
            } else {
                int j = i - 1024;
                int d = (j >= 448); if (d) j -= 448;
                row = j >> 2; kc = j & 3;
                src = (d ? B_lo : B_hi) + (size_t)row * KDIM + k0 + kc * 8;
                dst_row = 256 + d * 112 + row;
            }
            uint32_t dst = sb + (uint32_t)((dst_row * 40 + kc * 8) * 2);
            CP_ASYNC16(dst, src);
        }
    };

    float acc[2][7][4];
#pragma unroll
    for (int mi = 0; mi < 2; mi++)
#pragma unroll
        for (int ni = 0; ni < 7; ni++)
#pragma unroll
            for (int r = 0; r < 4; r++) acc[mi][ni][r] = 0.f;

    // prologue: stages 0..STAGES-2
#pragma unroll
    for (int s = 0; s < TC_STAGES - 1; s++) { load_stage(s, s * 32); CP_COMMIT(); }

    const int a_row = lane & 15, a_kh = lane >> 4;            // ldmatrix.x4 lane map
    const int b_row = lane & 7,  b_kh = (lane >> 3) & 1;      // ldmatrix.x2 lane map

    for (int it = 0; it < KITERS; it++) {
        CP_WAIT(TC_STAGES - 2);
        __syncthreads();
        if (it + TC_STAGES - 1 < KITERS) load_stage((it + TC_STAGES - 1) % TC_STAGES,
                                                    (it + TC_STAGES - 1) * 32);
        CP_COMMIT();

        const uint32_t sb = smem_base + (uint32_t)((it % TC_STAGES) * STAGE_ELEMS * 2);
#pragma unroll
        for (int ks = 0; ks < 2; ks++) {
            uint32_t af[2][2][4];   // [d][mi]
#pragma unroll
            for (int d = 0; d < 2; d++)
#pragma unroll
                for (int mi = 0; mi < 2; mi++) {
                    int r = d * 128 + warp_m * 32 + mi * 16 + a_row;
                    int c = ks * 16 + a_kh * 8;
                    ldsm_x4(af[d][mi], sb + (uint32_t)((r * 40 + c) * 2));
                }
            uint32_t bf[2][7][2];   // [d][ni]
#pragma unroll
            for (int d = 0; d < 2; d++)
#pragma unroll
                for (int ni = 0; ni < 7; ni++) {
                    int r = 256 + d * 112 + warp_n * 56 + ni * 8 + b_row;
                    int c = ks * 16 + b_kh * 8;
                    ldsm_x2(bf[d][ni], sb + (uint32_t)((r * 40 + c) * 2));
                }
#pragma unroll
            for (int mi = 0; mi < 2; mi++)
#pragma unroll
                for (int ni = 0; ni < 7; ni++) {
                    mma_16816(acc[mi][ni], af[0][mi], bf[0][ni]);   // hi*hi
                    mma_16816(acc[mi][ni], af[0][mi], bf[1][ni]);   // hi*lo
                    mma_16816(acc[mi][ni], af[1][mi], bf[0][ni]);   // lo*hi
                }
        }
        __syncthreads();
    }

    // ---- epilogue: bias + direct stores ----
    const int region = m0 / rowsPerRegion;
    const int mloc = m0 % rowsPerRegion;
    const float* bias = (region == 0) ? bias0 : (region == 1) ? bias1 : bias2;
    float* outp = ((region == 0) ? out0 : (region == 1) ? out1 : out2)
                  + (size_t)img * rowsPerRegion * 784 + (size_t)mloc * 784;

#pragma unroll
    for (int mi = 0; mi < 2; mi++) {
        int r0 = warp_m * 32 + mi * 16 + (lane >> 2);
        float bv0 = bias[mloc + r0];
        float bv1 = bias[mloc + r0 + 8];
#pragma unroll
        for (int ni = 0; ni < 7; ni++) {
            int col = n0 + warp_n * 56 + ni * 8 + (lane & 3) * 2;
            float2 v0 = make_float2(acc[mi][ni][0] + bv0, acc[mi][ni][1] + bv0);
            float2 v1 = make_float2(acc[mi][ni][2] + bv1, acc[mi][ni][3] + bv1);
            *reinterpret_cast<float2*>(outp + (size_t)r0 * 784 + col) = v0;
            *reinterpret_cast<float2*>(outp + (size_t)(r0 + 8) * 784 + col) = v1;
        }
    }
}

// ====================== 2x2 maxpool ======================
__global__ void pool_kernel()
{
    const int idx = blockIdx.x * 256 + threadIdx.x;
    const float* in = blockIdx.y ? ppre_buf : gpre_buf;
    float* outp     = blockIdx.y ? ppool_buf : gpool_buf;
    int pw = idx % 14;
    int r  = idx / 14;
    int ph = r % 14;
    r /= 14;
    const float* p = in + r * 784 + ph * 56 + pw * 2;
    outp[idx] = fmaxf(fmaxf(p[0], p[1]), fmaxf(p[28], p[29]));
}

// ====================== M[b] = (Phi_b @ G_b^T) / 1568 ======================
__global__ __launch_bounds__(256) void gemm_nt_M()
{
    const int b = blockIdx.z;
    const float* A  = ppool_buf + b * 401408;
    const float* Bm = gpool_buf + b * 401408;
    const int i0 = blockIdx.y * 64;
    const int j0 = blockIdx.x * 64;

    __shared__ float As[16][64];
    __shared__ float Bs[16][64];
    float acc[4][4] = {};

    const int tx = threadIdx.x, ty = threadIdx.y;
    const int tid = ty * 16 + tx;
    const int lr = tid >> 2;
    const int lk = (tid & 3) * 4;

    for (int k0 = 0; k0 < 1568; k0 += 16) {
        float4 av = *reinterpret_cast<const float4*>(A  + (i0 + lr) * 1568 + k0 + lk);
        float4 bv = *reinterpret_cast<const float4*>(Bm + (j0 + lr) * 1568 + k0 + lk);
        As[lk + 0][lr] = av.x; As[lk + 1][lr] = av.y; As[lk + 2][lr] = av.z; As[lk + 3][lr] = av.w;
        Bs[lk + 0][lr] = bv.x; Bs[lk + 1][lr] = bv.y; Bs[lk + 2][lr] = bv.z; Bs[lk + 3][lr] = bv.w;
        __syncthreads();
#pragma unroll
        for (int k = 0; k < 16; k++) {
            float4 a = *reinterpret_cast<float4*>(&As[k][ty * 4]);
            float4 b2 = *reinterpret_cast<float4*>(&Bs[k][tx * 4]);
            acc[0][0] += a.x * b2.x; acc[0][1] += a.x * b2.y; acc[0][2] += a.x * b2.z; acc[0][3] += a.x * b2.w;
            acc[1][0] += a.y * b2.x; acc[1][1] += a.y * b2.y; acc[1][2] += a.y * b2.z; acc[1][3] += a.y * b2.w;
            acc[2][0] += a.z * b2.x; acc[2][1] += a.z * b2.y; acc[2][2] += a.z * b2.z; acc[2][3] += a.z * b2.w;
            acc[3][0] += a.w * b2.x; acc[3][1] += a.w * b2.y; acc[3][2] += a.w * b2.z; acc[3][3] += a.w * b2.w;
        }
        __syncthreads();
    }

    float* C = Mmat_buf + b * 65536;
    const float inv = 1.0f / 1568.0f;
#pragma unroll
    for (int i = 0; i < 4; i++)
#pragma unroll
        for (int j = 0; j < 4; j++)
            C[(i0 + ty * 4 + i) * 256 + j0 + tx * 4 + j] = acc[i][j] * inv;
}

// ====================== y[b] = Theta_b^T @ M_b -> yt bf16 hi/lo ======================
__global__ __launch_bounds__(256) void gemm_tn_y()
{
    const int b = blockIdx.z;
    const float* A  = theta_buf + b * 1605632;   // A[k][m], ld 6272
    const float* Bm = Mmat_buf  + b * 65536;     // B[k][n], ld 256
    const int m0 = blockIdx.y * 64;
    const int n0 = blockIdx.x * 64;

    __shared__ float As[16][64];
    __shared__ float Bs[16][64];
    float acc[4][4] = {};

    const int tx = threadIdx.x, ty = threadIdx.y;
    const int tid = ty * 16 + tx;
    const int lk = tid >> 4;
    const int lq = (tid & 15) * 4;

    for (int k0 = 0; k0 < 256; k0 += 16) {
        *reinterpret_cast<float4*>(&As[lk][lq]) =
            *reinterpret_cast<const float4*>(A + (k0 + lk) * 6272 + m0 + lq);
        *reinterpret_cast<float4*>(&Bs[lk][lq]) =
            *reinterpret_cast<const float4*>(Bm + (k0 + lk) * 256 + n0 + lq);
        __syncthreads();
#pragma unroll
        for (int k = 0; k < 16; k++) {
            float4 a = *reinterpret_cast<float4*>(&As[k][ty * 4]);
            float4 b2 = *reinterpret_cast<float4*>(&Bs[k][tx * 4]);
            acc[0][0] += a.x * b2.x; acc[0][1] += a.x * b2.y; acc[0][2] += a.x * b2.z; acc[0][3] += a.x * b2.w;
            acc[1][0] += a.y * b2.x; acc[1][1] += a.y * b2.y; acc[1][2] += a.y * b2.z; acc[1][3] += a.y * b2.w;
            acc[2][0] += a.z * b2.x; acc[2][1] += a.z * b2.y; acc[2][2] += a.z * b2.z; acc[2][3] += a.z * b2.w;
            acc[3][0] += a.w * b2.x; acc[3][1] += a.w * b2.y; acc[3][2] += a.w * b2.z; acc[3][3] += a.w * b2.w;
        }
        __syncthreads();
    }

    // y (b, t=m, ci'=n): img = 8b + (n>>5); c = (n&31)*8 + t/784; s = t%784
    // store K-major for z-GEMM: yt[img][s][c], split bf16 hi/lo
#pragma unroll
    for (int i = 0; i < 4; i++) {
        int m = m0 + ty * 4 + i;
        int tq = m / 784, s = m % 784;
#pragma unroll
        for (int j = 0; j < 4; j++) {
            int n = n0 + tx * 4 + j;
            size_t dst = ((size_t)(8 * b + (n >> 5)) * 784 + s) * 256 + ((n & 31) * 8 + tq);
            split_store(acc[i][j], yt_hi, yt_lo, dst);
        }
    }
}

// ====================== BN stats + BN/residual ======================
__global__ __launch_bounds__(256) void bn_stats()
{
    const int c = blockIdx.x;
    float s1 = 0.f, s2 = 0.f;
    const float* base = z_buf + c * 784;
    for (int n = 0; n < 64; n++) {
        const float* p = base + n * 401408;
        for (int s = threadIdx.x; s < 784; s += 256) {
            float v = p[s];
            s1 += v; s2 += v * v;
        }
    }
    __shared__ float r1[256], r2[256];
    r1[threadIdx.x] = s1; r2[threadIdx.x] = s2;
    __syncthreads();
    for (int off = 128; off > 0; off >>= 1) {
        if (threadIdx.x < off) {
            r1[threadIdx.x] += r1[threadIdx.x + off];
            r2[threadIdx.x] += r2[threadIdx.x + off];
        }
        __syncthreads();
    }
    if (threadIdx.x == 0) { g_stats[c] = r1[0]; g_stats[512 + c] = r2[0]; }
}

__global__ __launch_bounds__(256) void bn_res(
    const float* __restrict__ x,
    const float* __restrict__ gamma, const float* __restrict__ beta,
    float* __restrict__ out)
{
    const int i4 = blockIdx.x * 256 + threadIdx.x;
    const int c = (i4 / 196) & 511;
    const float inv_cnt = 1.0f / 50176.0f;
    float mean = g_stats[c] * inv_cnt;
    float var  = g_stats[512 + c] * inv_cnt - mean * mean;
    float sc = gamma[c] * rsqrtf(var + 1e-5f);
    float sh = beta[c] - mean * sc;
    float4 zv = reinterpret_cast<const float4*>(z_buf)[i4];
    float4 xv = reinterpret_cast<const float4*>(x)[i4];
    float4 o;
    o.x = zv.x * sc + sh + xv.x;
    o.y = zv.y * sc + sh + xv.y;
    o.z = zv.z * sc + sh + xv.z;
    o.w = zv.w * sc + sh + xv.w;
    reinterpret_cast<float4*>(out)[i4] = o;
}

// ====================== launcher ======================
extern "C" void kernel_launch(void* const* d_in, const int* in_sizes, int n_in,
                              void* d_out, int out_size)
{
    const float* x     = (const float*)d_in[0];
    const float* wg    = (const float*)d_in[1];
    const float* bg    = (const float*)d_in[2];
    const float* wth   = (const float*)d_in[3];
    const float* bth   = (const float*)d_in[4];
    const float* wph   = (const float*)d_in[5];
    const float* bph   = (const float*)d_in[6];
    const float* wW    = (const float*)d_in[7];
    const float* bW    = (const float*)d_in[8];
    const float* gamma = (const float*)d_in[9];
    const float* beta  = (const float*)d_in[10];
    float* out = (float*)d_out;

    cudaFuncSetAttribute(mma_conv_gemm<512>,
                         cudaFuncAttributeMaxDynamicSharedMemorySize, TC_SMEM);
    cudaFuncSetAttribute(mma_conv_gemm<256>,
                         cudaFuncAttributeMaxDynamicSharedMemorySize, TC_SMEM);

    __nv_bfloat16 *p_wcat_hi, *p_wcat_lo, *p_wW_hi, *p_wW_lo;
    __nv_bfloat16 *p_xt_hi, *p_xt_lo, *p_yt_hi, *p_yt_lo;
    float *p_theta, *p_gpre, *p_ppre, *p_z;
    cudaGetSymbolAddress((void**)&p_wcat_hi, wcat_hi);
    cudaGetSymbolAddress((void**)&p_wcat_lo, wcat_lo);
    cudaGetSymbolAddress((void**)&p_wW_hi, wW_hi);
    cudaGetSymbolAddress((void**)&p_wW_lo, wW_lo);
    cudaGetSymbolAddress((void**)&p_xt_hi, xt_hi);
    cudaGetSymbolAddress((void**)&p_xt_lo, xt_lo);
    cudaGetSymbolAddress((void**)&p_yt_hi, yt_hi);
    cudaGetSymbolAddress((void**)&p_yt_lo, yt_lo);
    cudaGetSymbolAddress((void**)&p_theta, theta_buf);
    cudaGetSymbolAddress((void**)&p_gpre, gpre_buf);
    cudaGetSymbolAddress((void**)&p_ppre, ppre_buf);
    cudaGetSymbolAddress((void**)&p_z, z_buf);

    split_w_kernel<<<2048, 256>>>(wth, wg, wph, wW);
    split_x_kernel<<<dim3(49, 32, 64), dim3(16, 16)>>>(x);

    // projections: Out[768, 784] per image = Wcat @ Xt^T  (theta | g | phi)
    mma_conv_gemm<512><<<dim3(7, 6, 64), 256, TC_SMEM>>>(
        p_wcat_hi, p_wcat_lo, p_xt_hi, p_xt_lo,
        p_theta, p_gpre, p_ppre, bth, bg, bph, 256);

    pool_kernel<<<dim3(12544, 2), 256>>>();
    gemm_nt_M<<<dim3(4, 4, 8), dim3(16, 16)>>>();
    gemm_tn_y<<<dim3(4, 98, 8), dim3(16, 16)>>>();

    // z = conv1x1(y, wW, bW): Out[512, 784] per image = wW @ yt^T
    mma_conv_gemm<256><<<dim3(7, 4, 64), 256, TC_SMEM>>>(
        p_wW_hi, p_wW_lo, p_yt_hi, p_yt_lo,
        p_z, p_z, p_z, bW, bW, bW, 512);

    bn_stats<<<512, 256>>>();
    bn_res<<<25088, 256>>>(x, gamma, beta, out);
}